// round 10
// baseline (speedup 1.0000x reference)
#include <cuda_runtime.h>

// Per-row cosine similarity:
//   out[i] = dot(q_i, d_i) / (||q_i|| * ||d_i||),  N = 262144 rows, D = 256 fp32.
// HBM-bound streaming at ~7 TB/s achieved. One warp per row; each lane loads
// ONE contiguous 32B chunk per stream via inline-PTX 256-bit load
// (ld.global.nc.v8.f32 -> LDG.E.256 on sm_103a), so a warp covers the whole
// 1KB row in a single load instruction per stream. Block-level smem staging
// keeps the output store coalesced (one 32B STG per block).

#define DIM 256
#define ROW_CHUNKS (DIM / 8)   // 32 x 32B chunks per 1KB row

struct f8 { float v[8]; };

__device__ __forceinline__ f8 ldg256(const float* __restrict__ p) {
    f8 r;
    asm("ld.global.nc.v8.f32 {%0,%1,%2,%3,%4,%5,%6,%7}, [%8];"
        : "=f"(r.v[0]), "=f"(r.v[1]), "=f"(r.v[2]), "=f"(r.v[3]),
          "=f"(r.v[4]), "=f"(r.v[5]), "=f"(r.v[6]), "=f"(r.v[7])
        : "l"(p));
    return r;
}

__global__ __launch_bounds__(256, 8)
void cosine_rows_v8_kernel(const float* __restrict__ q,
                           const float* __restrict__ d,
                           float* __restrict__ out,
                           int n_rows) {
    __shared__ float s_res[8];

    const int warp_in_block = threadIdx.x >> 5;
    const int lane = threadIdx.x & 31;
    const int row = blockIdx.x * (blockDim.x >> 5) + warp_in_block;

    // Byte-contiguous: lane's 8 floats start at row*256 + lane*8.
    const long long base = (long long)row * DIM + lane * 8;

    // One 256-bit load per input stream: warp covers the full row.
    f8 qv = ldg256(q + base);
    f8 dv = ldg256(d + base);

    float qq = 0.f, dd = 0.f, qd = 0.f;
    #pragma unroll
    for (int i = 0; i < 8; i++) {
        qq = fmaf(qv.v[i], qv.v[i], qq);
        dd = fmaf(dv.v[i], dv.v[i], dd);
        qd = fmaf(qv.v[i], dv.v[i], qd);
    }

    #pragma unroll
    for (int off = 16; off > 0; off >>= 1) {
        qq += __shfl_xor_sync(0xFFFFFFFFu, qq, off);
        dd += __shfl_xor_sync(0xFFFFFFFFu, dd, off);
        qd += __shfl_xor_sync(0xFFFFFFFFu, qd, off);
    }

    if (lane == 0) {
        s_res[warp_in_block] = qd * rsqrtf(qq * dd);
    }
    __syncthreads();

    // One coalesced 32B store per block.
    if (threadIdx.x < 8) {
        const int out_base = blockIdx.x * 8;
        if (out_base + (int)threadIdx.x < n_rows) {
            out[out_base + threadIdx.x] = s_res[threadIdx.x];
        }
    }
}

extern "C" void kernel_launch(void* const* d_in, const int* in_sizes, int n_in,
                              void* d_out, int out_size) {
    const float* q = (const float*)d_in[0];
    const float* d = (const float*)d_in[1];
    float* out = (float*)d_out;

    const int n_rows = in_sizes[0] / DIM;  // 262144 (multiple of 8)

    const int threads = 256;               // 8 warps -> 8 rows per block
    const int rows_per_block = threads / 32;
    const int blocks = (n_rows + rows_per_block - 1) / rows_per_block;  // 32768

    cosine_rows_v8_kernel<<<blocks, threads>>>(q, d, out, n_rows);
}

// round 16
// speedup vs baseline: 1.0540x; 1.0540x over previous
#include <cuda_runtime.h>

// Per-row cosine similarity:
//   out[i] = dot(q_i, d_i) / (||q_i|| * ||d_i||),  N = 262144 rows, D = 256 fp32.
// HBM-bound streaming at the achieved-BW ceiling (~7 TB/s). R7 winning shape
// (1 row per warp, float4 streaming loads, smem-staged coalesced output store),
// with 512-thread blocks: 16 rows/block, one 64B store per block, half the CTA
// count of the R7 version.

#define DIM 256
#define ROW_F4 (DIM / 4)   // 64 float4 per row

__global__ __launch_bounds__(512, 4)
void cosine_rows_stg512_kernel(const float4* __restrict__ q,
                               const float4* __restrict__ d,
                               float* __restrict__ out,
                               int n_rows) {
    __shared__ float s_res[16];

    const int warp_in_block = threadIdx.x >> 5;
    const int lane = threadIdx.x & 31;
    const int row = blockIdx.x * (blockDim.x >> 5) + warp_in_block;

    const long long base = (long long)row * ROW_F4;

    // 4 independent 128B-coalesced streaming loads (touch-once data).
    float4 q0 = __ldcs(&q[base + lane]);
    float4 q1 = __ldcs(&q[base + lane + 32]);
    float4 d0 = __ldcs(&d[base + lane]);
    float4 d1 = __ldcs(&d[base + lane + 32]);

    float qq = q0.x * q0.x + q0.y * q0.y + q0.z * q0.z + q0.w * q0.w
             + q1.x * q1.x + q1.y * q1.y + q1.z * q1.z + q1.w * q1.w;
    float dd = d0.x * d0.x + d0.y * d0.y + d0.z * d0.z + d0.w * d0.w
             + d1.x * d1.x + d1.y * d1.y + d1.z * d1.z + d1.w * d1.w;
    float qd = q0.x * d0.x + q0.y * d0.y + q0.z * d0.z + q0.w * d0.w
             + q1.x * d1.x + q1.y * d1.y + q1.z * d1.z + q1.w * d1.w;

    #pragma unroll
    for (int off = 16; off > 0; off >>= 1) {
        qq += __shfl_xor_sync(0xFFFFFFFFu, qq, off);
        dd += __shfl_xor_sync(0xFFFFFFFFu, dd, off);
        qd += __shfl_xor_sync(0xFFFFFFFFu, qd, off);
    }

    if (lane == 0) {
        s_res[warp_in_block] = qd * rsqrtf(qq * dd);
    }
    __syncthreads();

    // One coalesced 64B store per block (lanes 0-15 of warp 0).
    if (threadIdx.x < 16) {
        const int out_base = blockIdx.x * 16;
        if (out_base + (int)threadIdx.x < n_rows) {
            out[out_base + threadIdx.x] = s_res[threadIdx.x];
        }
    }
}

extern "C" void kernel_launch(void* const* d_in, const int* in_sizes, int n_in,
                              void* d_out, int out_size) {
    const float4* q = (const float4*)d_in[0];
    const float4* d = (const float4*)d_in[1];
    float* out = (float*)d_out;

    const int n_rows = in_sizes[0] / DIM;  // 262144 (multiple of 16)

    const int threads = 512;               // 16 warps -> 16 rows per block
    const int rows_per_block = threads / 32;
    const int blocks = (n_rows + rows_per_block - 1) / rows_per_block;  // 16384

    cosine_rows_stg512_kernel<<<blocks, threads>>>(q, d, out, n_rows);
}